// round 11
// baseline (speedup 1.0000x reference)
#include <cuda_runtime.h>

#define Bdim 4
#define Ldim 512
#define Ddim 128
#define Hdim 128
#define G4   512            // 4*H
#define NROWS (Bdim*Ldim)   // 2048
#define EPSV 1e-5f

// ---------------- scratch (device globals; no allocation) ----------------
__device__ float g_q[NROWS*Ddim];
__device__ float g_k[NROWS*Ddim];
__device__ float g_v[NROWS*Ddim];
__device__ float g_attn[NROWS*Ddim];
__device__ float g_bnscale[3][Ddim];
__device__ float g_bnshift[3][Ddim];
__device__ float g_U[3][NROWS*G4];
__device__ float g_h1[3][NROWS*Hdim];
__device__ float g_U2[3][NROWS*G4];
__device__ float g_h2[3][NROWS*Hdim];
// transposed weights: [layer][branch][k4*512 + j] as float4 (k-major, gate j lane-contiguous)
__device__ float g_wtih[2][3][G4*Ddim];
__device__ float g_wthh[2][3][G4*Hdim];

// ---------------- helpers ----------------
__device__ __forceinline__ float fast_tanh(float x) {
    float e = __expf(2.f * x);
    return 1.f - __fdividef(2.f, e + 1.f);
}
__device__ __forceinline__ float fast_sigmoid(float x) {
    return __fdividef(1.f, 1.f + __expf(-x));
}
// Blackwell packed f32x2 FMA: two independent fp32 FMAs per issue
__device__ __forceinline__ unsigned long long ffma2(unsigned long long a,
                                                    unsigned long long b,
                                                    unsigned long long c) {
    unsigned long long d;
    asm("fma.rn.f32x2 %0, %1, %2, %3;" : "=l"(d) : "l"(a), "l"(b), "l"(c));
    return d;
}
__device__ __forceinline__ float pairsum(unsigned long long d) {
    float lo = __uint_as_float((unsigned)(d & 0xffffffffull));
    float hi = __uint_as_float((unsigned)(d >> 32));
    return lo + hi;
}
__device__ __forceinline__ unsigned int smem_u32(const void* p) {
    return (unsigned int)__cvta_generic_to_shared(p);
}
// acquire at CLUSTER scope: pairs with .release.cluster remote arrives
__device__ __forceinline__ void mbar_wait_cluster(unsigned int mbar, unsigned int parity) {
    asm volatile(
        "{\n\t"
        ".reg .pred P;\n\t"
        "WAITLOOP_%=:\n\t"
        "mbarrier.try_wait.parity.acquire.cluster.shared::cta.b64 P, [%0], %1, 0x989680;\n\t"
        "@P bra.uni DONE_%=;\n\t"
        "bra.uni WAITLOOP_%=;\n\t"
        "DONE_%=:\n\t"
        "}"
        :: "r"(mbar), "r"(parity) : "memory");
}

// block reductions for 128 threads
__device__ __forceinline__ float bredsum(float v, float* buf) {
    int tid = threadIdx.x;
    buf[tid] = v; __syncthreads();
    #pragma unroll
    for (int s = 64; s > 0; s >>= 1) {
        if (tid < s) buf[tid] += buf[tid + s];
        __syncthreads();
    }
    float r = buf[0]; __syncthreads();
    return r;
}
__device__ __forceinline__ float bredmax(float v, float* buf) {
    int tid = threadIdx.x;
    buf[tid] = v; __syncthreads();
    #pragma unroll
    for (int s = 64; s > 0; s >>= 1) {
        if (tid < s) buf[tid] = fmaxf(buf[tid], buf[tid + s]);
        __syncthreads();
    }
    float r = buf[0]; __syncthreads();
    return r;
}

// ---------------- kernel 0: weight transpose (run once per replay) ----------------
// grid (32, 12), block 512.  16384 float4 entries per matrix: linear = k4*512 + j
__global__ void transpose_kernel(const float* __restrict__ w1i, const float* __restrict__ w1h,
                                 const float* __restrict__ w2i, const float* __restrict__ w2h,
                                 const float* __restrict__ w3i, const float* __restrict__ w3h) {
    int m = blockIdx.y;
    int type = m / 6;            // 0 = ih, 1 = hh
    int r = m % 6;
    int layer = r / 3;
    int br = r % 3;
    const float* W;
    if (type == 0) W = ((br == 0) ? w1i : (br == 1) ? w2i : w3i) + layer * G4 * Ddim;
    else           W = ((br == 0) ? w1h : (br == 1) ? w2h : w3h) + layer * G4 * Hdim;
    float* out = (type == 0) ? g_wtih[layer][br] : g_wthh[layer][br];
    int linear = blockIdx.x * 512 + threadIdx.x;   // 0..16383  (k4*512 + j), float4 units
    int k4 = linear >> 9;
    int j = linear & 511;
    float4 v = *(const float4*)(W + j * Ddim + 4 * k4);
    ((float4*)out)[linear] = v;
}

// ---------------- kernel 1: q/k/v projections ----------------
// grid (256, 3), block 128.
__global__ void qkv_kernel(const float* __restrict__ x,
                           const float* __restrict__ Wq,
                           const float* __restrict__ Wk,
                           const float* __restrict__ bk,
                           const float* __restrict__ Wv) {
    int mat = blockIdx.y;
    const float* W = (mat == 0) ? Wq : (mat == 1) ? Wk : Wv;
    float* out = (mat == 0) ? g_q : (mat == 1) ? g_k : g_v;
    int row0 = blockIdx.x * 8;
    int tid = threadIdx.x;
    __shared__ __align__(16) float xs[8][Ddim];
    #pragma unroll
    for (int r = 0; r < 8; r++) xs[r][tid] = x[(row0 + r) * Ddim + tid];
    __syncthreads();
    float acc[8] = {0, 0, 0, 0, 0, 0, 0, 0};
    const float4* w4 = (const float4*)(W + tid * Ddim);
    #pragma unroll 8
    for (int k4 = 0; k4 < 32; k4++) {
        float4 w = w4[k4];
        #pragma unroll
        for (int r = 0; r < 8; r++) {
            float4 xv = ((const float4*)xs[r])[k4];
            acc[r] += xv.x * w.x + xv.y * w.y + xv.z * w.z + xv.w * w.w;
        }
    }
    float bb = (mat == 1) ? bk[tid] : 0.f;
    #pragma unroll
    for (int r = 0; r < 8; r++) out[(row0 + r) * Ddim + tid] = acc[r] + bb;
}

// ---------------- kernel 2: fused triple attention ----------------
// grid (L, B), block 128. One block computes attn_out[b, i, :].
__global__ void attn_kernel(const float* __restrict__ x,
                            const float* __restrict__ attn_w,
                            const float* __restrict__ attn_scale) {
    int i = blockIdx.x, b = blockIdx.y;
    int tid = threadIdx.x;
    __shared__ __align__(16) float xi[Ddim];
    __shared__ __align__(16) float qi[Ddim];
    __shared__ float s1[Ldim], s2[Ldim], s3[Ldim];
    __shared__ float red[128];

    const float* xb = x + b * Ldim * Ddim;
    const float* qb = g_q + b * Ldim * Ddim;
    const float* kb = g_k + b * Ldim * Ddim;
    const float* vb = g_v + b * Ldim * Ddim;

    xi[tid] = xb[i * Ddim + tid];
    qi[tid] = qb[i * Ddim + tid];
    __syncthreads();

    float sc2 = attn_scale[0] * rsqrtf((float)Ddim);

    for (int j = tid; j <= i; j += 128) {
        const float4* xj = (const float4*)(xb + j * Ddim);
        const float4* kj = (const float4*)(kb + j * Ddim);
        float a1 = 0.f, a2 = 0.f, a3 = 0.f;
        #pragma unroll 8
        for (int k4 = 0; k4 < 32; k4++) {
            float4 xv = xj[k4];
            float4 xiv = ((const float4*)xi)[k4];
            float4 kv = kj[k4];
            float4 qv = ((const float4*)qi)[k4];
            a1 += xiv.x * xv.x + xiv.y * xv.y + xiv.z * xv.z + xiv.w * xv.w;
            a2 += qv.x * kv.x + qv.y * kv.y + qv.z * kv.z + qv.w * kv.w;
            a3 += fast_tanh(xiv.x + xv.x) + fast_tanh(xiv.y + xv.y)
                + fast_tanh(xiv.z + xv.z) + fast_tanh(xiv.w + xv.w);
        }
        s1[j] = a1;
        s2[j] = a2 * sc2;
        s3[j] = a3;
    }
    __syncthreads();

    float m1 = -1e30f, m2 = -1e30f, m3 = -1e30f;
    for (int j = tid; j <= i; j += 128) {
        m1 = fmaxf(m1, s1[j]); m2 = fmaxf(m2, s2[j]); m3 = fmaxf(m3, s3[j]);
    }
    m1 = bredmax(m1, red);
    m2 = bredmax(m2, red);
    m3 = bredmax(m3, red);

    float t1 = 0.f, t2 = 0.f, t3 = 0.f;
    for (int j = tid; j <= i; j += 128) {
        float e1 = __expf(s1[j] - m1); s1[j] = e1; t1 += e1;
        float e2 = __expf(s2[j] - m2); s2[j] = e2; t2 += e2;
        float e3 = __expf(s3[j] - m3); s3[j] = e3; t3 += e3;
    }
    float S1 = bredsum(t1, red);
    float S2 = bredsum(t2, red);
    float S3 = bredsum(t3, red);

    float a1 = 0.f, a2 = 0.f, a3 = 0.f;
    const float* xcol = xb + tid;
    const float* vcol = vb + tid;
    #pragma unroll 4
    for (int j = 0; j <= i; j++) {
        float p1 = s1[j], p2 = s2[j], p3 = s3[j];
        float xv = xcol[j * Ddim];
        float vv = vcol[j * Ddim];
        a1 += p1 * xv;
        a2 += p2 * vv;
        a3 += p3 * xv;
    }
    float w0 = attn_w[0], w1 = attn_w[1], w2 = attn_w[2];
    float inv = 1.f / (w0 + w1 + w2);
    float r1 = 1.f / S1, r2 = 1.f / S2, r3 = 1.f / S3;
    g_attn[(b * Ldim + i) * Ddim + tid] =
        (w0 * a1 * r1 + w1 * a2 * r2 + w2 * a3 * r3) * inv;
}

// ---------------- kernel 3: batchnorm stats ----------------
// grid (128, 3), block 256.
__global__ void bnstat_kernel(const float* __restrict__ x,
                              const float* __restrict__ g1, const float* __restrict__ b1,
                              const float* __restrict__ g2, const float* __restrict__ b2,
                              const float* __restrict__ g3, const float* __restrict__ b3) {
    int c = blockIdx.x, br = blockIdx.y, tid = threadIdx.x;
    float s = 0.f, ss = 0.f;
    for (int n = tid; n < NROWS; n += 256) {
        float xv = x[n * Ddim + c];
        float av = g_attn[n * Ddim + c];
        float v = (br == 0) ? xv : (br == 1) ? (xv + av) : av;
        s += v; ss += v * v;
    }
    __shared__ float bs[256], bss[256];
    bs[tid] = s; bss[tid] = ss; __syncthreads();
    #pragma unroll
    for (int st = 128; st > 0; st >>= 1) {
        if (tid < st) { bs[tid] += bs[tid + st]; bss[tid] += bss[tid + st]; }
        __syncthreads();
    }
    if (tid == 0) {
        float m = bs[0] * (1.f / NROWS);
        float var = bss[0] * (1.f / NROWS) - m * m;
        float rstd = rsqrtf(var + EPSV);
        const float* g = (br == 0) ? g1 : (br == 1) ? g2 : g3;
        const float* bb = (br == 0) ? b1 : (br == 1) ? b2 : b3;
        float sc = rstd * g[c];
        g_bnscale[br][c] = sc;
        g_bnshift[br][c] = bb[c] - m * sc;
    }
}

// ---------------- kernel 4: LSTM input projection (transposed weights) ----------------
// grid (512, 3), block 512. 4 rows per block, thread = gate j, coalesced weight loads.
__global__ void __launch_bounds__(512)
uproj_kernel(const float* __restrict__ x, int layer,
             const float* __restrict__ bih0, const float* __restrict__ bhh0,
             const float* __restrict__ bih1, const float* __restrict__ bhh1,
             const float* __restrict__ bih2, const float* __restrict__ bhh2) {
    int br = blockIdx.y;
    const float4* wt = (const float4*)g_wtih[layer][br];
    const float* bi = ((br == 0) ? bih0 : (br == 1) ? bih1 : bih2) + layer * G4;
    const float* bh = ((br == 0) ? bhh0 : (br == 1) ? bhh1 : bhh2) + layer * G4;
    float* U = (layer == 0) ? g_U[br] : g_U2[br];
    int row0 = blockIdx.x * 4;
    int tid = threadIdx.x;
    __shared__ __align__(16) float xs[4][Ddim];
    {
        int r = tid >> 7, c = tid & 127;     // 512 threads -> exactly one element each
        float v;
        if (layer == 0) {
            float xv = x[(row0 + r) * Ddim + c];
            float av = g_attn[(row0 + r) * Ddim + c];
            float in = (br == 0) ? xv : (br == 1) ? (xv + av) : av;
            v = in * g_bnscale[br][c] + g_bnshift[br][c];
        } else {
            v = g_h1[br][(row0 + r) * Hdim + c];
        }
        xs[r][c] = v;
    }
    __syncthreads();
    int j = tid;
    float acc[4] = {0, 0, 0, 0};
    #pragma unroll 8
    for (int k4 = 0; k4 < 32; k4++) {
        float4 w = wt[k4 * 512 + j];          // coalesced: warp reads 512 B contiguous
        #pragma unroll
        for (int r = 0; r < 4; r++) {
            float4 h = ((const float4*)xs[r])[k4];
            acc[r] += w.x * h.x + w.y * h.y + w.z * h.z + w.w * h.w;
        }
    }
    float bias = bi[j] + bh[j];
    #pragma unroll
    for (int r = 0; r < 4; r++) U[(row0 + r) * G4 + j] = acc[r] + bias;
}

// ---------------- kernel 5: 2-CTA cluster scan, RF-resident Whh, mbarrier sync --------
// grid (2, Bdim, 3), cluster (2,1,1), block 512.
// CTA rank r owns gates [r*256, r*256+256). Thread pair (tid, tid+256) splits a gate row
// into two 64-float k-halves (16 ulonglong2 = 64 regs -> whole Whh in the 2 RFs).
// Per step: dot -> producers (tid<256) apply the gate nonlinearity, store the activated
// value locally AND into the peer's zact (st.shared::cluster), then issue a
// mbarrier.arrive.release.CLUSTER on the peer's mbarrier (count=256). The .cluster scope
// on the release is what R9 was missing: it orders this thread's remote store with the
// consumer's acquire.cluster try_wait. Local half is ordered by __syncthreads.
// Double-buffered by step parity; buffer reuse at t+2 is fenced by the arrive chain.
__global__ void __cluster_dims__(2, 1, 1) __launch_bounds__(512, 1)
scan_kernel(int layer) {
    unsigned int rank;
    asm("mov.u32 %0, %%cluster_ctarank;" : "=r"(rank));
    int b = blockIdx.y, br = blockIdx.z;
    const ulonglong2* wt = (const ulonglong2*)g_wthh[layer][br];  // [k4*512 + j]
    const float* U = ((layer == 0) ? g_U[br] : g_U2[br]) + b * Ldim * G4;
    float* hout = ((layer == 0) ? g_h1[br] : g_h2[br]) + b * Ldim * Hdim;
    int tid = threadIdx.x;
    int gate = tid & 255;            // local gate index
    int half = tid >> 8;             // k-half (0: k 0..63, 1: k 64..127)
    int jg = (int)rank * 256 + gate; // global gate 0..511
    unsigned int peer = rank ^ 1u;

    __shared__ __align__(16) float hs[Hdim];
    __shared__ float cs[Hdim];
    __shared__ float sp[512];
    __shared__ __align__(16) float zact[2][G4];
    __shared__ __align__(8) unsigned long long mbar[2];

    if (tid < Hdim) { hs[tid] = 0.f; cs[tid] = 0.f; }
    if (tid == 0) {
        asm volatile("mbarrier.init.shared.b64 [%0], 256;"
                     :: "r"(smem_u32(&mbar[0])) : "memory");
        asm volatile("mbarrier.init.shared.b64 [%0], 256;"
                     :: "r"(smem_u32(&mbar[1])) : "memory");
    }

    // whole weight slice in registers: 16 ulonglong2 = 64 floats (static indices)
    ulonglong2 wreg[16];
    #pragma unroll
    for (int m = 0; m < 16; m++) wreg[m] = wt[(half * 16 + m) * 512 + jg];
    __syncthreads();
    // one-time cluster barrier: both CTAs' mbarrier init visible before any remote arrive
    asm volatile("barrier.cluster.arrive.aligned;" ::: "memory");
    asm volatile("barrier.cluster.wait.aligned;" ::: "memory");

    // hoist remote addresses (peer's zact slot for this thread's gate, peer's mbarriers)
    unsigned int r_z[2], r_mb[2];
    if (tid < 256) {
        int zl = (int)rank * 256 + tid;
        unsigned int la0 = smem_u32(&zact[0][zl]);
        unsigned int la1 = smem_u32(&zact[1][zl]);
        unsigned int lm0 = smem_u32(&mbar[0]);
        unsigned int lm1 = smem_u32(&mbar[1]);
        asm("mapa.shared::cluster.u32 %0, %1, %2;" : "=r"(r_z[0]) : "r"(la0), "r"(peer));
        asm("mapa.shared::cluster.u32 %0, %1, %2;" : "=r"(r_z[1]) : "r"(la1), "r"(peer));
        asm("mapa.shared::cluster.u32 %0, %1, %2;" : "=r"(r_mb[0]) : "r"(lm0), "r"(peer));
        asm("mapa.shared::cluster.u32 %0, %1, %2;" : "=r"(r_mb[1]) : "r"(lm1), "r"(peer));
    }

    for (int t = 0; t < Ldim; t++) {
        int buf = t & 1;
        float u = 0.f;
        if (tid < 256) u = U[t * G4 + (int)rank * 256 + tid];   // prefetch
        const ulonglong2* hv = (const ulonglong2*)(hs + half * 64);
        unsigned long long a0 = 0ull, a1 = 0ull, a2 = 0ull, a3 = 0ull;
        #pragma unroll
        for (int m = 0; m < 16; m += 4) {
            a0 = ffma2(wreg[m+0].x, hv[m+0].x, a0);
            a1 = ffma2(wreg[m+0].y, hv[m+0].y, a1);
            a2 = ffma2(wreg[m+1].x, hv[m+1].x, a2);
            a3 = ffma2(wreg[m+1].y, hv[m+1].y, a3);
            a0 = ffma2(wreg[m+2].x, hv[m+2].x, a0);
            a1 = ffma2(wreg[m+2].y, hv[m+2].y, a1);
            a2 = ffma2(wreg[m+3].x, hv[m+3].x, a2);
            a3 = ffma2(wreg[m+3].y, hv[m+3].y, a3);
        }
        sp[tid] = pairsum(a0) + pairsum(a1) + pairsum(a2) + pairsum(a3);
        __syncthreads();
        if (tid < 256) {
            float z = sp[tid] + sp[tid + 256] + u;
            // gate nonlinearity applied 256-wide: i/f/o sigmoid, g tanh
            float a = (jg >= 256 && jg < 384) ? fast_tanh(z) : fast_sigmoid(z);
            zact[buf][(int)rank * 256 + tid] = a;       // local copy
            asm volatile("st.shared::cluster.f32 [%0], %1;"
                         :: "r"(r_z[buf]), "f"(a) : "memory");
            // RELEASE AT CLUSTER SCOPE: orders this thread's remote store with the
            // peer's acquire.cluster wait (the missing qualifier in R9).
            asm volatile("mbarrier.arrive.release.cluster.shared::cluster.b64 _, [%0];"
                         :: "r"(r_mb[buf]) : "memory");
        }
        __syncthreads();                                // local half ordering
        mbar_wait_cluster(smem_u32(&mbar[buf]), (unsigned)((t >> 1) & 1));
        if (tid < Hdim) {
            float ai = zact[buf][tid],       af = zact[buf][128 + tid];
            float ag = zact[buf][256 + tid], ao = zact[buf][384 + tid];
            float cn = af * cs[tid] + ai * ag;
            float hn = ao * fast_tanh(cn);
            cs[tid] = cn;
            hs[tid] = hn;
            if (rank == 0) hout[t * Hdim + tid] = hn;   // single writer
        }
        __syncthreads();
    }
}

// ---------------- kernel 6: weighted sum + layernorm ----------------
// grid 2048, block 128
__global__ void final_kernel(const float* __restrict__ sum_w,
                             const float* __restrict__ ln_g,
                             const float* __restrict__ ln_b,
                             float* __restrict__ out) {
    int row = blockIdx.x, tid = threadIdx.x;
    float w0 = sum_w[0], w1 = sum_w[1], w2 = sum_w[2];
    float inv = 1.f / (w0 + w1 + w2);
    float v = (w0 * g_h2[0][row * Hdim + tid]
             + w1 * g_h2[1][row * Hdim + tid]
             + w2 * g_h2[2][row * Hdim + tid]) * inv;
    __shared__ float buf[128];
    float m = bredsum(v, buf) * (1.f / Hdim);
    float d = v - m;
    float var = bredsum(d * d, buf) * (1.f / Hdim);
    out[row * Hdim + tid] = d * rsqrtf(var + EPSV) * ln_g[tid] + ln_b[tid];
}

// ---------------- launch ----------------
extern "C" void kernel_launch(void* const* d_in, const int* in_sizes, int n_in,
                              void* d_out, int out_size) {
    const float* x          = (const float*)d_in[0];
    const float* attn_w     = (const float*)d_in[1];
    const float* attn_scale = (const float*)d_in[2];
    const float* Wq         = (const float*)d_in[3];
    const float* Wk         = (const float*)d_in[4];
    const float* bk         = (const float*)d_in[5];
    const float* Wv         = (const float*)d_in[6];
    const float* bn1g = (const float*)d_in[7],  *bn1b = (const float*)d_in[8];
    const float* bn2g = (const float*)d_in[9],  *bn2b = (const float*)d_in[10];
    const float* bn3g = (const float*)d_in[11], *bn3b = (const float*)d_in[12];
    const float* l1_Wih = (const float*)d_in[13], *l1_Whh = (const float*)d_in[14];
    const float* l1_bih = (const float*)d_in[15], *l1_bhh = (const float*)d_in[16];
    const float* l2_Wih = (const float*)d_in[17], *l2_Whh = (const float*)d_in[18];
    const float* l2_bih = (const float*)d_in[19], *l2_bhh = (const float*)d_in[20];
    const float* l3_Wih = (const float*)d_in[21], *l3_Whh = (const float*)d_in[22];
    const float* l3_bih = (const float*)d_in[23], *l3_bhh = (const float*)d_in[24];
    const float* ln_g  = (const float*)d_in[25];
    const float* ln_b  = (const float*)d_in[26];
    const float* sum_w = (const float*)d_in[27];
    float* out = (float*)d_out;

    transpose_kernel<<<dim3(32, 12), 512>>>(l1_Wih, l1_Whh, l2_Wih, l2_Whh, l3_Wih, l3_Whh);
    qkv_kernel<<<dim3(256, 3), 128>>>(x, Wq, Wk, bk, Wv);
    attn_kernel<<<dim3(Ldim, Bdim), 128>>>(x, attn_w, attn_scale);
    bnstat_kernel<<<dim3(128, 3), 256>>>(x, bn1g, bn1b, bn2g, bn2b, bn3g, bn3b);
    uproj_kernel<<<dim3(512, 3), 512>>>(x, 0,
        l1_bih, l1_bhh, l2_bih, l2_bhh, l3_bih, l3_bhh);
    scan_kernel<<<dim3(2, Bdim, 3), 512>>>(0);
    uproj_kernel<<<dim3(512, 3), 512>>>(x, 1,
        l1_bih, l1_bhh, l2_bih, l2_bhh, l3_bih, l3_bhh);
    scan_kernel<<<dim3(2, Bdim, 3), 512>>>(1);
    final_kernel<<<NROWS, 128>>>(sum_w, ln_g, ln_b, out);
}

// round 12
// speedup vs baseline: 1.0498x; 1.0498x over previous
#include <cuda_runtime.h>

#define Bdim 4
#define Ldim 512
#define Ddim 128
#define Hdim 128
#define G4   512            // 4*H
#define NROWS (Bdim*Ldim)   // 2048
#define EPSV 1e-5f

// ---------------- scratch (device globals; no allocation) ----------------
__device__ float g_q[NROWS*Ddim];
__device__ float g_k[NROWS*Ddim];
__device__ float g_v[NROWS*Ddim];
__device__ float g_ex[NROWS*Ddim];     // exp(2*x) for additive-attention identity
__device__ float g_attn[NROWS*Ddim];
__device__ float g_bnscale[3][Ddim];
__device__ float g_bnshift[3][Ddim];
__device__ float g_U[3][NROWS*G4];
__device__ float g_h1[3][NROWS*Hdim];
__device__ float g_U2[3][NROWS*G4];
__device__ float g_h2[3][NROWS*Hdim];
// transposed weights: [layer][branch][k4*512 + j] as float4 (k-major, gate j lane-contiguous)
__device__ float g_wtih[2][3][G4*Ddim];
__device__ float g_wthh[2][3][G4*Hdim];

// ---------------- helpers ----------------
__device__ __forceinline__ float fast_tanh(float x) {
    float e = __expf(2.f * x);
    return 1.f - __fdividef(2.f, e + 1.f);
}
__device__ __forceinline__ float fast_sigmoid(float x) {
    return __fdividef(1.f, 1.f + __expf(-x));
}
// Blackwell packed f32x2 FMA: two independent fp32 FMAs per issue
__device__ __forceinline__ unsigned long long ffma2(unsigned long long a,
                                                    unsigned long long b,
                                                    unsigned long long c) {
    unsigned long long d;
    asm("fma.rn.f32x2 %0, %1, %2, %3;" : "=l"(d) : "l"(a), "l"(b), "l"(c));
    return d;
}
__device__ __forceinline__ float pairsum(unsigned long long d) {
    float lo = __uint_as_float((unsigned)(d & 0xffffffffull));
    float hi = __uint_as_float((unsigned)(d >> 32));
    return lo + hi;
}
__device__ __forceinline__ unsigned int smem_u32(const void* p) {
    return (unsigned int)__cvta_generic_to_shared(p);
}

// block reductions for 128 threads
__device__ __forceinline__ float bredsum(float v, float* buf) {
    int tid = threadIdx.x;
    buf[tid] = v; __syncthreads();
    #pragma unroll
    for (int s = 64; s > 0; s >>= 1) {
        if (tid < s) buf[tid] += buf[tid + s];
        __syncthreads();
    }
    float r = buf[0]; __syncthreads();
    return r;
}
__device__ __forceinline__ float bredmax(float v, float* buf) {
    int tid = threadIdx.x;
    buf[tid] = v; __syncthreads();
    #pragma unroll
    for (int s = 64; s > 0; s >>= 1) {
        if (tid < s) buf[tid] = fmaxf(buf[tid], buf[tid + s]);
        __syncthreads();
    }
    float r = buf[0]; __syncthreads();
    return r;
}

// ---------------- kernel 0: weight transpose (run once per replay) ----------------
// grid (32, 12), block 512.  16384 float4 entries per matrix: linear = k4*512 + j
__global__ void transpose_kernel(const float* __restrict__ w1i, const float* __restrict__ w1h,
                                 const float* __restrict__ w2i, const float* __restrict__ w2h,
                                 const float* __restrict__ w3i, const float* __restrict__ w3h) {
    int m = blockIdx.y;
    int type = m / 6;            // 0 = ih, 1 = hh
    int r = m % 6;
    int layer = r / 3;
    int br = r % 3;
    const float* W;
    if (type == 0) W = ((br == 0) ? w1i : (br == 1) ? w2i : w3i) + layer * G4 * Ddim;
    else           W = ((br == 0) ? w1h : (br == 1) ? w2h : w3h) + layer * G4 * Hdim;
    float* out = (type == 0) ? g_wtih[layer][br] : g_wthh[layer][br];
    int linear = blockIdx.x * 512 + threadIdx.x;   // 0..16383  (k4*512 + j), float4 units
    int k4 = linear >> 9;
    int j = linear & 511;
    float4 v = *(const float4*)(W + j * Ddim + 4 * k4);
    ((float4*)out)[linear] = v;
}

// ---------------- kernel 1: q/k/v projections + exp(2x) precompute ----------------
// grid (256, 3), block 128.
__global__ void qkv_kernel(const float* __restrict__ x,
                           const float* __restrict__ Wq,
                           const float* __restrict__ Wk,
                           const float* __restrict__ bk,
                           const float* __restrict__ Wv) {
    int mat = blockIdx.y;
    const float* W = (mat == 0) ? Wq : (mat == 1) ? Wk : Wv;
    float* out = (mat == 0) ? g_q : (mat == 1) ? g_k : g_v;
    int row0 = blockIdx.x * 8;
    int tid = threadIdx.x;
    __shared__ __align__(16) float xs[8][Ddim];
    #pragma unroll
    for (int r = 0; r < 8; r++) {
        float xv = x[(row0 + r) * Ddim + tid];
        xs[r][tid] = xv;
        if (mat == 0) g_ex[(row0 + r) * Ddim + tid] = __expf(2.f * xv);
    }
    __syncthreads();
    float acc[8] = {0, 0, 0, 0, 0, 0, 0, 0};
    const float4* w4 = (const float4*)(W + tid * Ddim);
    #pragma unroll 8
    for (int k4 = 0; k4 < 32; k4++) {
        float4 w = w4[k4];
        #pragma unroll
        for (int r = 0; r < 8; r++) {
            float4 xv = ((const float4*)xs[r])[k4];
            acc[r] += xv.x * w.x + xv.y * w.y + xv.z * w.z + xv.w * w.w;
        }
    }
    float bb = (mat == 1) ? bk[tid] : 0.f;
    #pragma unroll
    for (int r = 0; r < 8; r++) out[(row0 + r) * Ddim + tid] = acc[r] + bb;
}

// ---------------- kernel 2: fused triple attention ----------------
// grid (L, B), block 128. One block computes attn_out[b, i, :].
// Score 3 uses tanh(xi+xj) = 1 - 2/(1 + e^{2xi} e^{2xj}): one MUFU rcp per element
// instead of exp+rcp, with E = exp(2x) precomputed (exact identity, no approximation).
__global__ void attn_kernel(const float* __restrict__ x,
                            const float* __restrict__ attn_w,
                            const float* __restrict__ attn_scale) {
    int i = blockIdx.x, b = blockIdx.y;
    int tid = threadIdx.x;
    __shared__ __align__(16) float xi[Ddim];
    __shared__ __align__(16) float qi[Ddim];
    __shared__ __align__(16) float ei[Ddim];
    __shared__ float s1[Ldim], s2[Ldim], s3[Ldim];
    __shared__ float red[128];

    const float* xb = x + b * Ldim * Ddim;
    const float* qb = g_q + b * Ldim * Ddim;
    const float* kb = g_k + b * Ldim * Ddim;
    const float* vb = g_v + b * Ldim * Ddim;
    const float* eb = g_ex + b * Ldim * Ddim;

    float xiv0 = xb[i * Ddim + tid];
    xi[tid] = xiv0;
    qi[tid] = qb[i * Ddim + tid];
    ei[tid] = __expf(2.f * xiv0);
    __syncthreads();

    float sc2 = attn_scale[0] * rsqrtf((float)Ddim);

    for (int j = tid; j <= i; j += 128) {
        const float4* xj = (const float4*)(xb + j * Ddim);
        const float4* kj = (const float4*)(kb + j * Ddim);
        const float4* ej = (const float4*)(eb + j * Ddim);
        float a1 = 0.f, a2 = 0.f, s = 0.f;
        #pragma unroll 8
        for (int k4 = 0; k4 < 32; k4++) {
            float4 xv = xj[k4];
            float4 xiv = ((const float4*)xi)[k4];
            float4 kv = kj[k4];
            float4 qv = ((const float4*)qi)[k4];
            float4 ev = ej[k4];
            float4 eiv = ((const float4*)ei)[k4];
            a1 += xiv.x * xv.x + xiv.y * xv.y + xiv.z * xv.z + xiv.w * xv.w;
            a2 += qv.x * kv.x + qv.y * kv.y + qv.z * kv.z + qv.w * kv.w;
            s += __fdividef(1.f, fmaf(eiv.x, ev.x, 1.f))
               + __fdividef(1.f, fmaf(eiv.y, ev.y, 1.f))
               + __fdividef(1.f, fmaf(eiv.z, ev.z, 1.f))
               + __fdividef(1.f, fmaf(eiv.w, ev.w, 1.f));
        }
        s1[j] = a1;
        s2[j] = a2 * sc2;
        s3[j] = 128.f - 2.f * s;     // sum_d tanh(xi_d + xj_d)
    }
    __syncthreads();

    float m1 = -1e30f, m2 = -1e30f, m3 = -1e30f;
    for (int j = tid; j <= i; j += 128) {
        m1 = fmaxf(m1, s1[j]); m2 = fmaxf(m2, s2[j]); m3 = fmaxf(m3, s3[j]);
    }
    m1 = bredmax(m1, red);
    m2 = bredmax(m2, red);
    m3 = bredmax(m3, red);

    float t1 = 0.f, t2 = 0.f, t3 = 0.f;
    for (int j = tid; j <= i; j += 128) {
        float e1 = __expf(s1[j] - m1); s1[j] = e1; t1 += e1;
        float e2 = __expf(s2[j] - m2); s2[j] = e2; t2 += e2;
        float e3 = __expf(s3[j] - m3); s3[j] = e3; t3 += e3;
    }
    float S1 = bredsum(t1, red);
    float S2 = bredsum(t2, red);
    float S3 = bredsum(t3, red);

    float a1 = 0.f, a2 = 0.f, a3 = 0.f;
    const float* xcol = xb + tid;
    const float* vcol = vb + tid;
    #pragma unroll 4
    for (int j = 0; j <= i; j++) {
        float p1 = s1[j], p2 = s2[j], p3 = s3[j];
        float xv = xcol[j * Ddim];
        float vv = vcol[j * Ddim];
        a1 += p1 * xv;
        a2 += p2 * vv;
        a3 += p3 * xv;
    }
    float w0 = attn_w[0], w1 = attn_w[1], w2 = attn_w[2];
    float inv = 1.f / (w0 + w1 + w2);
    float r1 = 1.f / S1, r2 = 1.f / S2, r3 = 1.f / S3;
    g_attn[(b * Ldim + i) * Ddim + tid] =
        (w0 * a1 * r1 + w1 * a2 * r2 + w2 * a3 * r3) * inv;
}

// ---------------- kernel 3: batchnorm stats ----------------
// grid (128, 3), block 256.
__global__ void bnstat_kernel(const float* __restrict__ x,
                              const float* __restrict__ g1, const float* __restrict__ b1,
                              const float* __restrict__ g2, const float* __restrict__ b2,
                              const float* __restrict__ g3, const float* __restrict__ b3) {
    int c = blockIdx.x, br = blockIdx.y, tid = threadIdx.x;
    float s = 0.f, ss = 0.f;
    for (int n = tid; n < NROWS; n += 256) {
        float xv = x[n * Ddim + c];
        float av = g_attn[n * Ddim + c];
        float v = (br == 0) ? xv : (br == 1) ? (xv + av) : av;
        s += v; ss += v * v;
    }
    __shared__ float bs[256], bss[256];
    bs[tid] = s; bss[tid] = ss; __syncthreads();
    #pragma unroll
    for (int st = 128; st > 0; st >>= 1) {
        if (tid < st) { bs[tid] += bs[tid + st]; bss[tid] += bss[tid + st]; }
        __syncthreads();
    }
    if (tid == 0) {
        float m = bs[0] * (1.f / NROWS);
        float var = bss[0] * (1.f / NROWS) - m * m;
        float rstd = rsqrtf(var + EPSV);
        const float* g = (br == 0) ? g1 : (br == 1) ? g2 : g3;
        const float* bb = (br == 0) ? b1 : (br == 1) ? b2 : b3;
        float sc = rstd * g[c];
        g_bnscale[br][c] = sc;
        g_bnshift[br][c] = bb[c] - m * sc;
    }
}

// ---------------- kernel 4: LSTM input projection (transposed weights) ----------------
// grid (512, 3), block 512. 4 rows per block, thread = gate j, coalesced weight loads.
__global__ void __launch_bounds__(512)
uproj_kernel(const float* __restrict__ x, int layer,
             const float* __restrict__ bih0, const float* __restrict__ bhh0,
             const float* __restrict__ bih1, const float* __restrict__ bhh1,
             const float* __restrict__ bih2, const float* __restrict__ bhh2) {
    int br = blockIdx.y;
    const float4* wt = (const float4*)g_wtih[layer][br];
    const float* bi = ((br == 0) ? bih0 : (br == 1) ? bih1 : bih2) + layer * G4;
    const float* bh = ((br == 0) ? bhh0 : (br == 1) ? bhh1 : bhh2) + layer * G4;
    float* U = (layer == 0) ? g_U[br] : g_U2[br];
    int row0 = blockIdx.x * 4;
    int tid = threadIdx.x;
    __shared__ __align__(16) float xs[4][Ddim];
    {
        int r = tid >> 7, c = tid & 127;     // 512 threads -> exactly one element each
        float v;
        if (layer == 0) {
            float xv = x[(row0 + r) * Ddim + c];
            float av = g_attn[(row0 + r) * Ddim + c];
            float in = (br == 0) ? xv : (br == 1) ? (xv + av) : av;
            v = in * g_bnscale[br][c] + g_bnshift[br][c];
        } else {
            v = g_h1[br][(row0 + r) * Hdim + c];
        }
        xs[r][c] = v;
    }
    __syncthreads();
    int j = tid;
    float acc[4] = {0, 0, 0, 0};
    #pragma unroll 8
    for (int k4 = 0; k4 < 32; k4++) {
        float4 w = wt[k4 * 512 + j];          // coalesced: warp reads 512 B contiguous
        #pragma unroll
        for (int r = 0; r < 4; r++) {
            float4 h = ((const float4*)xs[r])[k4];
            acc[r] += w.x * h.x + w.y * h.y + w.z * h.z + w.w * h.w;
        }
    }
    float bias = bi[j] + bh[j];
    #pragma unroll
    for (int r = 0; r < 4; r++) U[(row0 + r) * G4 + j] = acc[r] + bias;
}

// ---------------- kernel 5: 2-CTA cluster scan, RF-resident Whh, cluster-barrier sync --
// (R10 version — proven fastest; mbarrier handshake measured slower in R11.)
__global__ void __cluster_dims__(2, 1, 1) __launch_bounds__(512, 1)
scan_kernel(int layer) {
    unsigned int rank;
    asm("mov.u32 %0, %%cluster_ctarank;" : "=r"(rank));
    int b = blockIdx.y, br = blockIdx.z;
    const ulonglong2* wt = (const ulonglong2*)g_wthh[layer][br];  // [k4*512 + j]
    const float* U = ((layer == 0) ? g_U[br] : g_U2[br]) + b * Ldim * G4;
    float* hout = ((layer == 0) ? g_h1[br] : g_h2[br]) + b * Ldim * Hdim;
    int tid = threadIdx.x;
    int gate = tid & 255;            // local gate index
    int half = tid >> 8;             // k-half (0: k 0..63, 1: k 64..127)
    int jg = (int)rank * 256 + gate; // global gate 0..511
    unsigned int peer = rank ^ 1u;

    __shared__ __align__(16) float hs[Hdim];
    __shared__ float cs[Hdim];
    __shared__ float sp[512];
    __shared__ __align__(16) float zact[2][G4];

    if (tid < Hdim) { hs[tid] = 0.f; cs[tid] = 0.f; }

    // whole weight slice in registers: 16 ulonglong2 = 64 floats (static indices)
    ulonglong2 wreg[16];
    #pragma unroll
    for (int m = 0; m < 16; m++) wreg[m] = wt[(half * 16 + m) * 512 + jg];
    __syncthreads();

    for (int t = 0; t < Ldim; t++) {
        int buf = t & 1;
        float u = 0.f;
        if (tid < 256) u = U[t * G4 + (int)rank * 256 + tid];   // prefetch
        const ulonglong2* hv = (const ulonglong2*)(hs + half * 64);
        unsigned long long a0 = 0ull, a1 = 0ull, a2 = 0ull, a3 = 0ull;
        #pragma unroll
        for (int m = 0; m < 16; m += 4) {
            a0 = ffma2(wreg[m+0].x, hv[m+0].x, a0);
            a1 = ffma2(wreg[m+0].y, hv[m+0].y, a1);
            a2 = ffma2(wreg[m+1].x, hv[m+1].x, a2);
            a3 = ffma2(wreg[m+1].y, hv[m+1].y, a3);
            a0 = ffma2(wreg[m+2].x, hv[m+2].x, a0);
            a1 = ffma2(wreg[m+2].y, hv[m+2].y, a1);
            a2 = ffma2(wreg[m+3].x, hv[m+3].x, a2);
            a3 = ffma2(wreg[m+3].y, hv[m+3].y, a3);
        }
        sp[tid] = pairsum(a0) + pairsum(a1) + pairsum(a2) + pairsum(a3);
        __syncthreads();
        if (tid < 256) {
            float z = sp[tid] + sp[tid + 256] + u;
            // gate nonlinearity applied 256-wide: i/f/o sigmoid, g tanh
            float a = (jg >= 256 && jg < 384) ? fast_tanh(z) : fast_sigmoid(z);
            int zl = (int)rank * 256 + tid;
            zact[buf][zl] = a;                          // local copy
            unsigned int la = smem_u32(&zact[buf][zl]);
            unsigned int ra;
            asm volatile("mapa.shared::cluster.u32 %0, %1, %2;"
                         : "=r"(ra) : "r"(la), "r"(peer));
            asm volatile("st.shared::cluster.f32 [%0], %1;"
                         :: "r"(ra), "f"(a) : "memory");
        }
        // one cluster barrier: publishes both activated halves to both CTAs
        asm volatile("barrier.cluster.arrive.aligned;" ::: "memory");
        asm volatile("barrier.cluster.wait.aligned;" ::: "memory");
        if (tid < Hdim) {
            float ai = zact[buf][tid],       af = zact[buf][128 + tid];
            float ag = zact[buf][256 + tid], ao = zact[buf][384 + tid];
            float cn = af * cs[tid] + ai * ag;
            float hn = ao * fast_tanh(cn);
            cs[tid] = cn;
            hs[tid] = hn;
            if (rank == 0) hout[t * Hdim + tid] = hn;   // single writer
        }
        __syncthreads();
    }
}

// ---------------- kernel 6: weighted sum + layernorm ----------------
// grid 2048, block 128
__global__ void final_kernel(const float* __restrict__ sum_w,
                             const float* __restrict__ ln_g,
                             const float* __restrict__ ln_b,
                             float* __restrict__ out) {
    int row = blockIdx.x, tid = threadIdx.x;
    float w0 = sum_w[0], w1 = sum_w[1], w2 = sum_w[2];
    float inv = 1.f / (w0 + w1 + w2);
    float v = (w0 * g_h2[0][row * Hdim + tid]
             + w1 * g_h2[1][row * Hdim + tid]
             + w2 * g_h2[2][row * Hdim + tid]) * inv;
    __shared__ float buf[128];
    float m = bredsum(v, buf) * (1.f / Hdim);
    float d = v - m;
    float var = bredsum(d * d, buf) * (1.f / Hdim);
    out[row * Hdim + tid] = d * rsqrtf(var + EPSV) * ln_g[tid] + ln_b[tid];
}

// ---------------- launch ----------------
extern "C" void kernel_launch(void* const* d_in, const int* in_sizes, int n_in,
                              void* d_out, int out_size) {
    const float* x          = (const float*)d_in[0];
    const float* attn_w     = (const float*)d_in[1];
    const float* attn_scale = (const float*)d_in[2];
    const float* Wq         = (const float*)d_in[3];
    const float* Wk         = (const float*)d_in[4];
    const float* bk         = (const float*)d_in[5];
    const float* Wv         = (const float*)d_in[6];
    const float* bn1g = (const float*)d_in[7],  *bn1b = (const float*)d_in[8];
    const float* bn2g = (const float*)d_in[9],  *bn2b = (const float*)d_in[10];
    const float* bn3g = (const float*)d_in[11], *bn3b = (const float*)d_in[12];
    const float* l1_Wih = (const float*)d_in[13], *l1_Whh = (const float*)d_in[14];
    const float* l1_bih = (const float*)d_in[15], *l1_bhh = (const float*)d_in[16];
    const float* l2_Wih = (const float*)d_in[17], *l2_Whh = (const float*)d_in[18];
    const float* l2_bih = (const float*)d_in[19], *l2_bhh = (const float*)d_in[20];
    const float* l3_Wih = (const float*)d_in[21], *l3_Whh = (const float*)d_in[22];
    const float* l3_bih = (const float*)d_in[23], *l3_bhh = (const float*)d_in[24];
    const float* ln_g  = (const float*)d_in[25];
    const float* ln_b  = (const float*)d_in[26];
    const float* sum_w = (const float*)d_in[27];
    float* out = (float*)d_out;

    transpose_kernel<<<dim3(32, 12), 512>>>(l1_Wih, l1_Whh, l2_Wih, l2_Whh, l3_Wih, l3_Whh);
    qkv_kernel<<<dim3(256, 3), 128>>>(x, Wq, Wk, bk, Wv);
    attn_kernel<<<dim3(Ldim, Bdim), 128>>>(x, attn_w, attn_scale);
    bnstat_kernel<<<dim3(128, 3), 256>>>(x, bn1g, bn1b, bn2g, bn2b, bn3g, bn3b);
    uproj_kernel<<<dim3(512, 3), 512>>>(x, 0,
        l1_bih, l1_bhh, l2_bih, l2_bhh, l3_bih, l3_bhh);
    scan_kernel<<<dim3(2, Bdim, 3), 512>>>(0);
    uproj_kernel<<<dim3(512, 3), 512>>>(x, 1,
        l1_bih, l1_bhh, l2_bih, l2_bhh, l3_bih, l3_bhh);
    scan_kernel<<<dim3(2, Bdim, 3), 512>>>(1);
    final_kernel<<<NROWS, 128>>>(sum_w, ln_g, ln_b, out);
}

// round 13
// speedup vs baseline: 1.1520x; 1.0974x over previous
#include <cuda_runtime.h>

#define Bdim 4
#define Ldim 512
#define Ddim 128
#define Hdim 128
#define G4   512            // 4*H
#define NROWS (Bdim*Ldim)   // 2048
#define EPSV 1e-5f

// ---------------- scratch (device globals; no allocation) ----------------
__device__ float g_q[NROWS*Ddim];
__device__ float g_k[NROWS*Ddim];
__device__ float g_v[NROWS*Ddim];
__device__ float g_attn[NROWS*Ddim];
__device__ float g_bnscale[3][Ddim];
__device__ float g_bnshift[3][Ddim];
__device__ float g_U[3][NROWS*G4];
__device__ float g_h1[3][NROWS*Hdim];
__device__ float g_U2[3][NROWS*G4];
__device__ float g_h2[3][NROWS*Hdim];
// transposed weights: [layer][branch][k4*512 + j] as float4 (k-major, gate j lane-contiguous)
__device__ float g_wtih[2][3][G4*Ddim];
__device__ float g_wthh[2][3][G4*Hdim];

// ---------------- helpers ----------------
__device__ __forceinline__ float fast_tanh(float x) {
    float e = __expf(2.f * x);
    return 1.f - __fdividef(2.f, e + 1.f);
}
__device__ __forceinline__ float fast_sigmoid(float x) {
    return __fdividef(1.f, 1.f + __expf(-x));
}
// Blackwell packed f32x2 FMA: two independent fp32 FMAs per issue
__device__ __forceinline__ unsigned long long ffma2(unsigned long long a,
                                                    unsigned long long b,
                                                    unsigned long long c) {
    unsigned long long d;
    asm("fma.rn.f32x2 %0, %1, %2, %3;" : "=l"(d) : "l"(a), "l"(b), "l"(c));
    return d;
}
__device__ __forceinline__ float pairsum(unsigned long long d) {
    float lo = __uint_as_float((unsigned)(d & 0xffffffffull));
    float hi = __uint_as_float((unsigned)(d >> 32));
    return lo + hi;
}
__device__ __forceinline__ unsigned int smem_u32(const void* p) {
    return (unsigned int)__cvta_generic_to_shared(p);
}

// block reductions for 128 threads
__device__ __forceinline__ float bredsum(float v, float* buf) {
    int tid = threadIdx.x;
    buf[tid] = v; __syncthreads();
    #pragma unroll
    for (int s = 64; s > 0; s >>= 1) {
        if (tid < s) buf[tid] += buf[tid + s];
        __syncthreads();
    }
    float r = buf[0]; __syncthreads();
    return r;
}
__device__ __forceinline__ float bredmax(float v, float* buf) {
    int tid = threadIdx.x;
    buf[tid] = v; __syncthreads();
    #pragma unroll
    for (int s = 64; s > 0; s >>= 1) {
        if (tid < s) buf[tid] = fmaxf(buf[tid], buf[tid + s]);
        __syncthreads();
    }
    float r = buf[0]; __syncthreads();
    return r;
}

// ---------------- kernel 0: weight transpose (run once per replay) ----------------
// grid (32, 12), block 512.  16384 float4 entries per matrix: linear = k4*512 + j
__global__ void transpose_kernel(const float* __restrict__ w1i, const float* __restrict__ w1h,
                                 const float* __restrict__ w2i, const float* __restrict__ w2h,
                                 const float* __restrict__ w3i, const float* __restrict__ w3h) {
    int m = blockIdx.y;
    int type = m / 6;            // 0 = ih, 1 = hh
    int r = m % 6;
    int layer = r / 3;
    int br = r % 3;
    const float* W;
    if (type == 0) W = ((br == 0) ? w1i : (br == 1) ? w2i : w3i) + layer * G4 * Ddim;
    else           W = ((br == 0) ? w1h : (br == 1) ? w2h : w3h) + layer * G4 * Hdim;
    float* out = (type == 0) ? g_wtih[layer][br] : g_wthh[layer][br];
    int linear = blockIdx.x * 512 + threadIdx.x;   // 0..16383  (k4*512 + j), float4 units
    int k4 = linear >> 9;
    int j = linear & 511;
    float4 v = *(const float4*)(W + j * Ddim + 4 * k4);
    ((float4*)out)[linear] = v;
}

// ---------------- kernel 1: q/k/v projections ----------------
// grid (256, 3), block 128.
__global__ void qkv_kernel(const float* __restrict__ x,
                           const float* __restrict__ Wq,
                           const float* __restrict__ Wk,
                           const float* __restrict__ bk,
                           const float* __restrict__ Wv) {
    int mat = blockIdx.y;
    const float* W = (mat == 0) ? Wq : (mat == 1) ? Wk : Wv;
    float* out = (mat == 0) ? g_q : (mat == 1) ? g_k : g_v;
    int row0 = blockIdx.x * 8;
    int tid = threadIdx.x;
    __shared__ __align__(16) float xs[8][Ddim];
    #pragma unroll
    for (int r = 0; r < 8; r++) xs[r][tid] = x[(row0 + r) * Ddim + tid];
    __syncthreads();
    float acc[8] = {0, 0, 0, 0, 0, 0, 0, 0};
    const float4* w4 = (const float4*)(W + tid * Ddim);
    #pragma unroll 8
    for (int k4 = 0; k4 < 32; k4++) {
        float4 w = w4[k4];
        #pragma unroll
        for (int r = 0; r < 8; r++) {
            float4 xv = ((const float4*)xs[r])[k4];
            acc[r] += xv.x * w.x + xv.y * w.y + xv.z * w.z + xv.w * w.w;
        }
    }
    float bb = (mat == 1) ? bk[tid] : 0.f;
    #pragma unroll
    for (int r = 0; r < 8; r++) out[(row0 + r) * Ddim + tid] = acc[r] + bb;
}

// ---------------- kernel 2: fused triple attention ----------------
// grid (L, B), block 128. One block computes attn_out[b, i, :].
// Phase 1 is warp-cooperative: one warp per j-row, lanes load consecutive float4s
// (coalesced LDG.128, 4 wavefronts) instead of one row per thread (32 wavefronts).
__global__ void attn_kernel(const float* __restrict__ x,
                            const float* __restrict__ attn_w,
                            const float* __restrict__ attn_scale) {
    int i = blockIdx.x, b = blockIdx.y;
    int tid = threadIdx.x;
    int lane = tid & 31, wid = tid >> 5;
    __shared__ __align__(16) float xi[Ddim];
    __shared__ __align__(16) float qi[Ddim];
    __shared__ float s1[Ldim], s2[Ldim], s3[Ldim];
    __shared__ float red[128];

    const float* xb = x + b * Ldim * Ddim;
    const float* qb = g_q + b * Ldim * Ddim;
    const float* kb = g_k + b * Ldim * Ddim;
    const float* vb = g_v + b * Ldim * Ddim;

    xi[tid] = xb[i * Ddim + tid];
    qi[tid] = qb[i * Ddim + tid];
    __syncthreads();

    float sc2 = attn_scale[0] * rsqrtf((float)Ddim);

    // phase 1: warp w handles rows j = w, w+4, ...  (lane slice = 4 channels)
    float4 xiv4 = ((const float4*)xi)[lane];
    float4 qiv4 = ((const float4*)qi)[lane];
    for (int j = wid; j <= i; j += 4) {
        float4 xv = ((const float4*)(xb + j * Ddim))[lane];   // coalesced
        float4 kv = ((const float4*)(kb + j * Ddim))[lane];   // coalesced
        float a1 = xiv4.x * xv.x + xiv4.y * xv.y + xiv4.z * xv.z + xiv4.w * xv.w;
        float a2 = qiv4.x * kv.x + qiv4.y * kv.y + qiv4.z * kv.z + qiv4.w * kv.w;
        float a3 = fast_tanh(xiv4.x + xv.x) + fast_tanh(xiv4.y + xv.y)
                 + fast_tanh(xiv4.z + xv.z) + fast_tanh(xiv4.w + xv.w);
        #pragma unroll
        for (int m = 16; m > 0; m >>= 1) {
            a1 += __shfl_xor_sync(0xffffffffu, a1, m);
            a2 += __shfl_xor_sync(0xffffffffu, a2, m);
            a3 += __shfl_xor_sync(0xffffffffu, a3, m);
        }
        if (lane == 0) { s1[j] = a1; s2[j] = a2 * sc2; s3[j] = a3; }
    }
    __syncthreads();

    float m1 = -1e30f, m2 = -1e30f, m3 = -1e30f;
    for (int j = tid; j <= i; j += 128) {
        m1 = fmaxf(m1, s1[j]); m2 = fmaxf(m2, s2[j]); m3 = fmaxf(m3, s3[j]);
    }
    m1 = bredmax(m1, red);
    m2 = bredmax(m2, red);
    m3 = bredmax(m3, red);

    float t1 = 0.f, t2 = 0.f, t3 = 0.f;
    for (int j = tid; j <= i; j += 128) {
        float e1 = __expf(s1[j] - m1); s1[j] = e1; t1 += e1;
        float e2 = __expf(s2[j] - m2); s2[j] = e2; t2 += e2;
        float e3 = __expf(s3[j] - m3); s3[j] = e3; t3 += e3;
    }
    float S1 = bredsum(t1, red);
    float S2 = bredsum(t2, red);
    float S3 = bredsum(t3, red);

    float a1 = 0.f, a2 = 0.f, a3 = 0.f;
    const float* xcol = xb + tid;
    const float* vcol = vb + tid;
    #pragma unroll 4
    for (int j = 0; j <= i; j++) {
        float p1 = s1[j], p2 = s2[j], p3 = s3[j];
        float xv = xcol[j * Ddim];
        float vv = vcol[j * Ddim];
        a1 += p1 * xv;
        a2 += p2 * vv;
        a3 += p3 * xv;
    }
    float w0 = attn_w[0], w1 = attn_w[1], w2 = attn_w[2];
    float inv = 1.f / (w0 + w1 + w2);
    float r1 = 1.f / S1, r2 = 1.f / S2, r3 = 1.f / S3;
    g_attn[(b * Ldim + i) * Ddim + tid] =
        (w0 * a1 * r1 + w1 * a2 * r2 + w2 * a3 * r3) * inv;
}

// ---------------- kernel 3: batchnorm stats ----------------
// grid (128, 3), block 256.
__global__ void bnstat_kernel(const float* __restrict__ x,
                              const float* __restrict__ g1, const float* __restrict__ b1,
                              const float* __restrict__ g2, const float* __restrict__ b2,
                              const float* __restrict__ g3, const float* __restrict__ b3) {
    int c = blockIdx.x, br = blockIdx.y, tid = threadIdx.x;
    float s = 0.f, ss = 0.f;
    for (int n = tid; n < NROWS; n += 256) {
        float xv = x[n * Ddim + c];
        float av = g_attn[n * Ddim + c];
        float v = (br == 0) ? xv : (br == 1) ? (xv + av) : av;
        s += v; ss += v * v;
    }
    __shared__ float bs[256], bss[256];
    bs[tid] = s; bss[tid] = ss; __syncthreads();
    #pragma unroll
    for (int st = 128; st > 0; st >>= 1) {
        if (tid < st) { bs[tid] += bs[tid + st]; bss[tid] += bss[tid + st]; }
        __syncthreads();
    }
    if (tid == 0) {
        float m = bs[0] * (1.f / NROWS);
        float var = bss[0] * (1.f / NROWS) - m * m;
        float rstd = rsqrtf(var + EPSV);
        const float* g = (br == 0) ? g1 : (br == 1) ? g2 : g3;
        const float* bb = (br == 0) ? b1 : (br == 1) ? b2 : b3;
        float sc = rstd * g[c];
        g_bnscale[br][c] = sc;
        g_bnshift[br][c] = bb[c] - m * sc;
    }
}

// ---------------- kernel 4: LSTM input projection (transposed weights) ----------------
// grid (512, 3), block 512. 4 rows per block, thread = gate j, coalesced weight loads.
__global__ void __launch_bounds__(512)
uproj_kernel(const float* __restrict__ x, int layer,
             const float* __restrict__ bih0, const float* __restrict__ bhh0,
             const float* __restrict__ bih1, const float* __restrict__ bhh1,
             const float* __restrict__ bih2, const float* __restrict__ bhh2) {
    int br = blockIdx.y;
    const float4* wt = (const float4*)g_wtih[layer][br];
    const float* bi = ((br == 0) ? bih0 : (br == 1) ? bih1 : bih2) + layer * G4;
    const float* bh = ((br == 0) ? bhh0 : (br == 1) ? bhh1 : bhh2) + layer * G4;
    float* U = (layer == 0) ? g_U[br] : g_U2[br];
    int row0 = blockIdx.x * 4;
    int tid = threadIdx.x;
    __shared__ __align__(16) float xs[4][Ddim];
    {
        int r = tid >> 7, c = tid & 127;     // 512 threads -> exactly one element each
        float v;
        if (layer == 0) {
            float xv = x[(row0 + r) * Ddim + c];
            float av = g_attn[(row0 + r) * Ddim + c];
            float in = (br == 0) ? xv : (br == 1) ? (xv + av) : av;
            v = in * g_bnscale[br][c] + g_bnshift[br][c];
        } else {
            v = g_h1[br][(row0 + r) * Hdim + c];
        }
        xs[r][c] = v;
    }
    __syncthreads();
    int j = tid;
    float acc[4] = {0, 0, 0, 0};
    #pragma unroll 8
    for (int k4 = 0; k4 < 32; k4++) {
        float4 w = wt[k4 * 512 + j];          // coalesced: warp reads 512 B contiguous
        #pragma unroll
        for (int r = 0; r < 4; r++) {
            float4 h = ((const float4*)xs[r])[k4];
            acc[r] += w.x * h.x + w.y * h.y + w.z * h.z + w.w * h.w;
        }
    }
    float bias = bi[j] + bh[j];
    #pragma unroll
    for (int r = 0; r < 4; r++) U[(row0 + r) * G4 + j] = acc[r] + bias;
}

// ---------------- kernel 5: 2-CTA cluster scan, RF-resident Whh, cluster-barrier sync --
// (R10 version — proven fastest; mbarrier handshake measured slower in R11.)
__global__ void __cluster_dims__(2, 1, 1) __launch_bounds__(512, 1)
scan_kernel(int layer) {
    unsigned int rank;
    asm("mov.u32 %0, %%cluster_ctarank;" : "=r"(rank));
    int b = blockIdx.y, br = blockIdx.z;
    const ulonglong2* wt = (const ulonglong2*)g_wthh[layer][br];  // [k4*512 + j]
    const float* U = ((layer == 0) ? g_U[br] : g_U2[br]) + b * Ldim * G4;
    float* hout = ((layer == 0) ? g_h1[br] : g_h2[br]) + b * Ldim * Hdim;
    int tid = threadIdx.x;
    int gate = tid & 255;            // local gate index
    int half = tid >> 8;             // k-half (0: k 0..63, 1: k 64..127)
    int jg = (int)rank * 256 + gate; // global gate 0..511
    unsigned int peer = rank ^ 1u;

    __shared__ __align__(16) float hs[Hdim];
    __shared__ float cs[Hdim];
    __shared__ float sp[512];
    __shared__ __align__(16) float zact[2][G4];

    if (tid < Hdim) { hs[tid] = 0.f; cs[tid] = 0.f; }

    // whole weight slice in registers: 16 ulonglong2 = 64 floats (static indices)
    ulonglong2 wreg[16];
    #pragma unroll
    for (int m = 0; m < 16; m++) wreg[m] = wt[(half * 16 + m) * 512 + jg];
    __syncthreads();

    for (int t = 0; t < Ldim; t++) {
        int buf = t & 1;
        float u = 0.f;
        if (tid < 256) u = U[t * G4 + (int)rank * 256 + tid];   // prefetch
        const ulonglong2* hv = (const ulonglong2*)(hs + half * 64);
        unsigned long long a0 = 0ull, a1 = 0ull, a2 = 0ull, a3 = 0ull;
        #pragma unroll
        for (int m = 0; m < 16; m += 4) {
            a0 = ffma2(wreg[m+0].x, hv[m+0].x, a0);
            a1 = ffma2(wreg[m+0].y, hv[m+0].y, a1);
            a2 = ffma2(wreg[m+1].x, hv[m+1].x, a2);
            a3 = ffma2(wreg[m+1].y, hv[m+1].y, a3);
            a0 = ffma2(wreg[m+2].x, hv[m+2].x, a0);
            a1 = ffma2(wreg[m+2].y, hv[m+2].y, a1);
            a2 = ffma2(wreg[m+3].x, hv[m+3].x, a2);
            a3 = ffma2(wreg[m+3].y, hv[m+3].y, a3);
        }
        sp[tid] = pairsum(a0) + pairsum(a1) + pairsum(a2) + pairsum(a3);
        __syncthreads();
        if (tid < 256) {
            float z = sp[tid] + sp[tid + 256] + u;
            // gate nonlinearity applied 256-wide: i/f/o sigmoid, g tanh
            float a = (jg >= 256 && jg < 384) ? fast_tanh(z) : fast_sigmoid(z);
            int zl = (int)rank * 256 + tid;
            zact[buf][zl] = a;                          // local copy
            unsigned int la = smem_u32(&zact[buf][zl]);
            unsigned int ra;
            asm volatile("mapa.shared::cluster.u32 %0, %1, %2;"
                         : "=r"(ra) : "r"(la), "r"(peer));
            asm volatile("st.shared::cluster.f32 [%0], %1;"
                         :: "r"(ra), "f"(a) : "memory");
        }
        // one cluster barrier: publishes both activated halves to both CTAs
        asm volatile("barrier.cluster.arrive.aligned;" ::: "memory");
        asm volatile("barrier.cluster.wait.aligned;" ::: "memory");
        if (tid < Hdim) {
            float ai = zact[buf][tid],       af = zact[buf][128 + tid];
            float ag = zact[buf][256 + tid], ao = zact[buf][384 + tid];
            float cn = af * cs[tid] + ai * ag;
            float hn = ao * fast_tanh(cn);
            cs[tid] = cn;
            hs[tid] = hn;
            if (rank == 0) hout[t * Hdim + tid] = hn;   // single writer
        }
        __syncthreads();
    }
}

// ---------------- kernel 6: weighted sum + layernorm ----------------
// grid 2048, block 128
__global__ void final_kernel(const float* __restrict__ sum_w,
                             const float* __restrict__ ln_g,
                             const float* __restrict__ ln_b,
                             float* __restrict__ out) {
    int row = blockIdx.x, tid = threadIdx.x;
    float w0 = sum_w[0], w1 = sum_w[1], w2 = sum_w[2];
    float inv = 1.f / (w0 + w1 + w2);
    float v = (w0 * g_h2[0][row * Hdim + tid]
             + w1 * g_h2[1][row * Hdim + tid]
             + w2 * g_h2[2][row * Hdim + tid]) * inv;
    __shared__ float buf[128];
    float m = bredsum(v, buf) * (1.f / Hdim);
    float d = v - m;
    float var = bredsum(d * d, buf) * (1.f / Hdim);
    out[row * Hdim + tid] = d * rsqrtf(var + EPSV) * ln_g[tid] + ln_b[tid];
}

// ---------------- launch ----------------
extern "C" void kernel_launch(void* const* d_in, const int* in_sizes, int n_in,
                              void* d_out, int out_size) {
    const float* x          = (const float*)d_in[0];
    const float* attn_w     = (const float*)d_in[1];
    const float* attn_scale = (const float*)d_in[2];
    const float* Wq         = (const float*)d_in[3];
    const float* Wk         = (const float*)d_in[4];
    const float* bk         = (const float*)d_in[5];
    const float* Wv         = (const float*)d_in[6];
    const float* bn1g = (const float*)d_in[7],  *bn1b = (const float*)d_in[8];
    const float* bn2g = (const float*)d_in[9],  *bn2b = (const float*)d_in[10];
    const float* bn3g = (const float*)d_in[11], *bn3b = (const float*)d_in[12];
    const float* l1_Wih = (const float*)d_in[13], *l1_Whh = (const float*)d_in[14];
    const float* l1_bih = (const float*)d_in[15], *l1_bhh = (const float*)d_in[16];
    const float* l2_Wih = (const float*)d_in[17], *l2_Whh = (const float*)d_in[18];
    const float* l2_bih = (const float*)d_in[19], *l2_bhh = (const float*)d_in[20];
    const float* l3_Wih = (const float*)d_in[21], *l3_Whh = (const float*)d_in[22];
    const float* l3_bih = (const float*)d_in[23], *l3_bhh = (const float*)d_in[24];
    const float* ln_g  = (const float*)d_in[25];
    const float* ln_b  = (const float*)d_in[26];
    const float* sum_w = (const float*)d_in[27];
    float* out = (float*)d_out;

    transpose_kernel<<<dim3(32, 12), 512>>>(l1_Wih, l1_Whh, l2_Wih, l2_Whh, l3_Wih, l3_Whh);
    qkv_kernel<<<dim3(256, 3), 128>>>(x, Wq, Wk, bk, Wv);
    attn_kernel<<<dim3(Ldim, Bdim), 128>>>(x, attn_w, attn_scale);
    bnstat_kernel<<<dim3(128, 3), 256>>>(x, bn1g, bn1b, bn2g, bn2b, bn3g, bn3b);
    uproj_kernel<<<dim3(512, 3), 512>>>(x, 0,
        l1_bih, l1_bhh, l2_bih, l2_bhh, l3_bih, l3_bhh);
    scan_kernel<<<dim3(2, Bdim, 3), 512>>>(0);
    uproj_kernel<<<dim3(512, 3), 512>>>(x, 1,
        l1_bih, l1_bhh, l2_bih, l2_bhh, l3_bih, l3_bhh);
    scan_kernel<<<dim3(2, Bdim, 3), 512>>>(1);
    final_kernel<<<NROWS, 128>>>(sum_w, ln_g, ln_b, out);
}

// round 14
// speedup vs baseline: 1.3173x; 1.1434x over previous
#include <cuda_runtime.h>

#define Bdim 4
#define Ldim 512
#define Ddim 128
#define Hdim 128
#define G4   512            // 4*H
#define NROWS (Bdim*Ldim)   // 2048
#define EPSV 1e-5f
#define CH   8              // pipeline chunk (timesteps)

// ---------------- scratch (device globals; no allocation) ----------------
__device__ float g_q[NROWS*Ddim];
__device__ float g_k[NROWS*Ddim];
__device__ float g_v[NROWS*Ddim];
__device__ float g_attn[NROWS*Ddim];
__device__ float g_bnscale[3][Ddim];
__device__ float g_bnshift[3][Ddim];
__device__ float g_U[3][NROWS*G4];
__device__ float g_h1[3][NROWS*Hdim];
__device__ float g_h2[3][NROWS*Hdim];
__device__ unsigned g_prog[3][Bdim];   // layer-1 scan progress (timesteps done)
// transposed weights: [layer][branch][k4*512 + j] as float4 (k-major, gate j lane-contiguous)
__device__ float g_wtih[2][3][G4*Ddim];
__device__ float g_wthh[2][3][G4*Hdim];

// ---------------- helpers ----------------
__device__ __forceinline__ float fast_tanh(float x) {
    float e = __expf(2.f * x);
    return 1.f - __fdividef(2.f, e + 1.f);
}
__device__ __forceinline__ float fast_sigmoid(float x) {
    return __fdividef(1.f, 1.f + __expf(-x));
}
__device__ __forceinline__ unsigned long long ffma2(unsigned long long a,
                                                    unsigned long long b,
                                                    unsigned long long c) {
    unsigned long long d;
    asm("fma.rn.f32x2 %0, %1, %2, %3;" : "=l"(d) : "l"(a), "l"(b), "l"(c));
    return d;
}
__device__ __forceinline__ float pairsum(unsigned long long d) {
    float lo = __uint_as_float((unsigned)(d & 0xffffffffull));
    float hi = __uint_as_float((unsigned)(d >> 32));
    return lo + hi;
}
__device__ __forceinline__ unsigned int smem_u32(const void* p) {
    return (unsigned int)__cvta_generic_to_shared(p);
}

__device__ __forceinline__ float bredsum(float v, float* buf) {
    int tid = threadIdx.x;
    buf[tid] = v; __syncthreads();
    #pragma unroll
    for (int s = 64; s > 0; s >>= 1) {
        if (tid < s) buf[tid] += buf[tid + s];
        __syncthreads();
    }
    float r = buf[0]; __syncthreads();
    return r;
}
__device__ __forceinline__ float bredmax(float v, float* buf) {
    int tid = threadIdx.x;
    buf[tid] = v; __syncthreads();
    #pragma unroll
    for (int s = 64; s > 0; s >>= 1) {
        if (tid < s) buf[tid] = fmaxf(buf[tid], buf[tid + s]);
        __syncthreads();
    }
    float r = buf[0]; __syncthreads();
    return r;
}

// ---------------- kernel 0: weight transpose ----------------
// grid (32, 12), block 512.
__global__ void transpose_kernel(const float* __restrict__ w1i, const float* __restrict__ w1h,
                                 const float* __restrict__ w2i, const float* __restrict__ w2h,
                                 const float* __restrict__ w3i, const float* __restrict__ w3h) {
    int m = blockIdx.y;
    int type = m / 6;
    int r = m % 6;
    int layer = r / 3;
    int br = r % 3;
    const float* W;
    if (type == 0) W = ((br == 0) ? w1i : (br == 1) ? w2i : w3i) + layer * G4 * Ddim;
    else           W = ((br == 0) ? w1h : (br == 1) ? w2h : w3h) + layer * G4 * Hdim;
    float* out = (type == 0) ? g_wtih[layer][br] : g_wthh[layer][br];
    int linear = blockIdx.x * 512 + threadIdx.x;
    int k4 = linear >> 9;
    int j = linear & 511;
    float4 v = *(const float4*)(W + j * Ddim + 4 * k4);
    ((float4*)out)[linear] = v;
}

// ---------------- kernel 1: q/k/v projections ----------------
__global__ void qkv_kernel(const float* __restrict__ x,
                           const float* __restrict__ Wq,
                           const float* __restrict__ Wk,
                           const float* __restrict__ bk,
                           const float* __restrict__ Wv) {
    int mat = blockIdx.y;
    const float* W = (mat == 0) ? Wq : (mat == 1) ? Wk : Wv;
    float* out = (mat == 0) ? g_q : (mat == 1) ? g_k : g_v;
    int row0 = blockIdx.x * 8;
    int tid = threadIdx.x;
    __shared__ __align__(16) float xs[8][Ddim];
    #pragma unroll
    for (int r = 0; r < 8; r++) xs[r][tid] = x[(row0 + r) * Ddim + tid];
    __syncthreads();
    float acc[8] = {0, 0, 0, 0, 0, 0, 0, 0};
    const float4* w4 = (const float4*)(W + tid * Ddim);
    #pragma unroll 8
    for (int k4 = 0; k4 < 32; k4++) {
        float4 w = w4[k4];
        #pragma unroll
        for (int r = 0; r < 8; r++) {
            float4 xv = ((const float4*)xs[r])[k4];
            acc[r] += xv.x * w.x + xv.y * w.y + xv.z * w.z + xv.w * w.w;
        }
    }
    float bb = (mat == 1) ? bk[tid] : 0.f;
    #pragma unroll
    for (int r = 0; r < 8; r++) out[(row0 + r) * Ddim + tid] = acc[r] + bb;
}

// ---------------- kernel 2: fused triple attention (R13 warp-cooperative) ----------------
__global__ void attn_kernel(const float* __restrict__ x,
                            const float* __restrict__ attn_w,
                            const float* __restrict__ attn_scale) {
    int i = blockIdx.x, b = blockIdx.y;
    int tid = threadIdx.x;
    int lane = tid & 31, wid = tid >> 5;
    __shared__ __align__(16) float xi[Ddim];
    __shared__ __align__(16) float qi[Ddim];
    __shared__ float s1[Ldim], s2[Ldim], s3[Ldim];
    __shared__ float red[128];

    const float* xb = x + b * Ldim * Ddim;
    const float* qb = g_q + b * Ldim * Ddim;
    const float* kb = g_k + b * Ldim * Ddim;
    const float* vb = g_v + b * Ldim * Ddim;

    xi[tid] = xb[i * Ddim + tid];
    qi[tid] = qb[i * Ddim + tid];
    __syncthreads();

    float sc2 = attn_scale[0] * rsqrtf((float)Ddim);

    float4 xiv4 = ((const float4*)xi)[lane];
    float4 qiv4 = ((const float4*)qi)[lane];
    for (int j = wid; j <= i; j += 4) {
        float4 xv = ((const float4*)(xb + j * Ddim))[lane];
        float4 kv = ((const float4*)(kb + j * Ddim))[lane];
        float a1 = xiv4.x * xv.x + xiv4.y * xv.y + xiv4.z * xv.z + xiv4.w * xv.w;
        float a2 = qiv4.x * kv.x + qiv4.y * kv.y + qiv4.z * kv.z + qiv4.w * kv.w;
        float a3 = fast_tanh(xiv4.x + xv.x) + fast_tanh(xiv4.y + xv.y)
                 + fast_tanh(xiv4.z + xv.z) + fast_tanh(xiv4.w + xv.w);
        #pragma unroll
        for (int m = 16; m > 0; m >>= 1) {
            a1 += __shfl_xor_sync(0xffffffffu, a1, m);
            a2 += __shfl_xor_sync(0xffffffffu, a2, m);
            a3 += __shfl_xor_sync(0xffffffffu, a3, m);
        }
        if (lane == 0) { s1[j] = a1; s2[j] = a2 * sc2; s3[j] = a3; }
    }
    __syncthreads();

    float m1 = -1e30f, m2 = -1e30f, m3 = -1e30f;
    for (int j = tid; j <= i; j += 128) {
        m1 = fmaxf(m1, s1[j]); m2 = fmaxf(m2, s2[j]); m3 = fmaxf(m3, s3[j]);
    }
    m1 = bredmax(m1, red);
    m2 = bredmax(m2, red);
    m3 = bredmax(m3, red);

    float t1 = 0.f, t2 = 0.f, t3 = 0.f;
    for (int j = tid; j <= i; j += 128) {
        float e1 = __expf(s1[j] - m1); s1[j] = e1; t1 += e1;
        float e2 = __expf(s2[j] - m2); s2[j] = e2; t2 += e2;
        float e3 = __expf(s3[j] - m3); s3[j] = e3; t3 += e3;
    }
    float S1 = bredsum(t1, red);
    float S2 = bredsum(t2, red);
    float S3 = bredsum(t3, red);

    float a1 = 0.f, a2 = 0.f, a3 = 0.f;
    const float* xcol = xb + tid;
    const float* vcol = vb + tid;
    #pragma unroll 4
    for (int j = 0; j <= i; j++) {
        float p1 = s1[j], p2 = s2[j], p3 = s3[j];
        float xv = xcol[j * Ddim];
        float vv = vcol[j * Ddim];
        a1 += p1 * xv;
        a2 += p2 * vv;
        a3 += p3 * xv;
    }
    float w0 = attn_w[0], w1 = attn_w[1], w2 = attn_w[2];
    float inv = 1.f / (w0 + w1 + w2);
    float r1 = 1.f / S1, r2 = 1.f / S2, r3 = 1.f / S3;
    g_attn[(b * Ldim + i) * Ddim + tid] =
        (w0 * a1 * r1 + w1 * a2 * r2 + w2 * a3 * r3) * inv;
}

// ---------------- kernel 3: batchnorm stats ----------------
__global__ void bnstat_kernel(const float* __restrict__ x,
                              const float* __restrict__ g1, const float* __restrict__ b1,
                              const float* __restrict__ g2, const float* __restrict__ b2,
                              const float* __restrict__ g3, const float* __restrict__ b3) {
    int c = blockIdx.x, br = blockIdx.y, tid = threadIdx.x;
    float s = 0.f, ss = 0.f;
    for (int n = tid; n < NROWS; n += 256) {
        float xv = x[n * Ddim + c];
        float av = g_attn[n * Ddim + c];
        float v = (br == 0) ? xv : (br == 1) ? (xv + av) : av;
        s += v; ss += v * v;
    }
    __shared__ float bs[256], bss[256];
    bs[tid] = s; bss[tid] = ss; __syncthreads();
    #pragma unroll
    for (int st = 128; st > 0; st >>= 1) {
        if (tid < st) { bs[tid] += bs[tid + st]; bss[tid] += bss[tid + st]; }
        __syncthreads();
    }
    if (tid == 0) {
        float m = bs[0] * (1.f / NROWS);
        float var = bss[0] * (1.f / NROWS) - m * m;
        float rstd = rsqrtf(var + EPSV);
        const float* g = (br == 0) ? g1 : (br == 1) ? g2 : g3;
        const float* bb = (br == 0) ? b1 : (br == 1) ? b2 : b3;
        float sc = rstd * g[c];
        g_bnscale[br][c] = sc;
        g_bnshift[br][c] = bb[c] - m * sc;
    }
}

// ---------------- kernel 4: layer-0 input projection + progress-flag reset ----------------
// grid (512, 3), block 512.
__global__ void __launch_bounds__(512)
uproj_kernel(const float* __restrict__ x,
             const float* __restrict__ bih0, const float* __restrict__ bhh0,
             const float* __restrict__ bih1, const float* __restrict__ bhh1,
             const float* __restrict__ bih2, const float* __restrict__ bhh2) {
    int br = blockIdx.y;
    if (blockIdx.x == 0 && threadIdx.x < Bdim) g_prog[br][threadIdx.x] = 0;  // reset flags
    const float4* wt = (const float4*)g_wtih[0][br];
    const float* bi = ((br == 0) ? bih0 : (br == 1) ? bih1 : bih2);
    const float* bh = ((br == 0) ? bhh0 : (br == 1) ? bhh1 : bhh2);
    float* U = g_U[br];
    int row0 = blockIdx.x * 4;
    int tid = threadIdx.x;
    __shared__ __align__(16) float xs[4][Ddim];
    {
        int r = tid >> 7, c = tid & 127;
        float xv = x[(row0 + r) * Ddim + c];
        float av = g_attn[(row0 + r) * Ddim + c];
        float in = (br == 0) ? xv : (br == 1) ? (xv + av) : av;
        xs[r][c] = in * g_bnscale[br][c] + g_bnshift[br][c];
    }
    __syncthreads();
    int j = tid;
    float acc[4] = {0, 0, 0, 0};
    #pragma unroll 8
    for (int k4 = 0; k4 < 32; k4++) {
        float4 w = wt[k4 * 512 + j];
        #pragma unroll
        for (int r = 0; r < 4; r++) {
            float4 h = ((const float4*)xs[r])[k4];
            acc[r] += w.x * h.x + w.y * h.y + w.z * h.z + w.w * h.w;
        }
    }
    float bias = bi[j] + bh[j];
    #pragma unroll
    for (int r = 0; r < 4; r++) U[(row0 + r) * G4 + j] = acc[r] + bias;
}

// ---------------- kernel 5: FUSED pipelined 2-layer scan ----------------
// grid (2, Bdim, 6), cluster (2,1,1), block 512.  blockIdx.z: br = z%3, lay = z/3.
// Layer-0 clusters: R10 scan on g_U, publishing progress every CH steps.
// Layer-1 clusters: poll progress, load h1 chunk, compute own input projection
// (Wih2 streamed, accumulators in regs), then scan the chunk.
__global__ void __cluster_dims__(2, 1, 1) __launch_bounds__(512, 1)
scan_fused(const float* __restrict__ bih0, const float* __restrict__ bhh0,
           const float* __restrict__ bih1, const float* __restrict__ bhh1,
           const float* __restrict__ bih2, const float* __restrict__ bhh2) {
    unsigned int rank;
    asm("mov.u32 %0, %%cluster_ctarank;" : "=r"(rank));
    int b = blockIdx.y;
    int zb = blockIdx.z;
    int br = zb % 3, lay = zb / 3;
    const ulonglong2* wt = (const ulonglong2*)g_wthh[lay][br];
    const float* U = g_U[br] + b * Ldim * G4;                      // lay 0 input
    const float* h1g = g_h1[br] + b * Ldim * Hdim;                 // lay 1 input
    float* hout = ((lay == 0) ? g_h1[br] : g_h2[br]) + b * Ldim * Hdim;
    int tid = threadIdx.x;
    int gate = tid & 255;
    int half = tid >> 8;
    int jg = (int)rank * 256 + gate;
    unsigned int peer = rank ^ 1u;

    __shared__ __align__(16) float hs[Hdim];
    __shared__ float cs[Hdim];
    __shared__ float sp[512];
    __shared__ __align__(16) float zact[2][G4];
    __shared__ __align__(16) float h1c[CH][Hdim];
    __shared__ float upart[CH][512];

    if (tid < Hdim) { hs[tid] = 0.f; cs[tid] = 0.f; }

    // Whh slice in registers (both layers)
    ulonglong2 wreg[16];
    #pragma unroll
    for (int m = 0; m < 16; m++) wreg[m] = wt[(half * 16 + m) * 512 + jg];

    // layer-1 bias per gate (held in reg by tid<256)
    float biasr = 0.f;
    if (lay == 1 && tid < 256) {
        const float* bi = ((br == 0) ? bih0 : (br == 1) ? bih1 : bih2);
        const float* bh = ((br == 0) ? bhh0 : (br == 1) ? bhh1 : bhh2);
        biasr = bi[G4 + jg] + bh[G4 + jg];
    }
    const ulonglong2* wih = (const ulonglong2*)g_wtih[1][br];
    __syncthreads();

    for (int c = 0; c < Ldim / CH; c++) {
        if (lay == 1) {
            // wait for producer to finish this chunk of h1
            if (tid == 0) {
                unsigned target = (unsigned)((c + 1) * CH);
                while (atomicAdd(&g_prog[br][b], 0u) < target) {}
                __threadfence();
            }
            __syncthreads();
            // load h1 chunk (CH*128 floats = 256 float4)
            if (tid < CH * 32) ((float4*)h1c)[tid] = ((const float4*)(h1g + c * CH * Hdim))[tid];
            __syncthreads();
            // chunk input projection: acc over k for CH timesteps, weights streamed
            unsigned long long a0[CH], a1[CH];
            #pragma unroll
            for (int t = 0; t < CH; t++) { a0[t] = 0ull; a1[t] = 0ull; }
            #pragma unroll
            for (int m = 0; m < 16; m++) {
                ulonglong2 wv = wih[(half * 16 + m) * 512 + jg];
                #pragma unroll
                for (int t = 0; t < CH; t++) {
                    const ulonglong2* hv = (const ulonglong2*)(h1c[t] + half * 64);
                    ulonglong2 h = hv[m];
                    a0[t] = ffma2(wv.x, h.x, a0[t]);
                    a1[t] = ffma2(wv.y, h.y, a1[t]);
                }
            }
            #pragma unroll
            for (int t = 0; t < CH; t++) upart[t][tid] = pairsum(a0[t]) + pairsum(a1[t]);
            __syncthreads();
        }

        for (int tt = 0; tt < CH; tt++) {
            int t = c * CH + tt;
            int buf = t & 1;
            float u = 0.f;
            if (lay == 0 && tid < 256) u = U[t * G4 + (int)rank * 256 + tid];
            const ulonglong2* hv = (const ulonglong2*)(hs + half * 64);
            unsigned long long d0 = 0ull, d1 = 0ull, d2 = 0ull, d3 = 0ull;
            #pragma unroll
            for (int m = 0; m < 16; m += 4) {
                d0 = ffma2(wreg[m+0].x, hv[m+0].x, d0);
                d1 = ffma2(wreg[m+0].y, hv[m+0].y, d1);
                d2 = ffma2(wreg[m+1].x, hv[m+1].x, d2);
                d3 = ffma2(wreg[m+1].y, hv[m+1].y, d3);
                d0 = ffma2(wreg[m+2].x, hv[m+2].x, d0);
                d1 = ffma2(wreg[m+2].y, hv[m+2].y, d1);
                d2 = ffma2(wreg[m+3].x, hv[m+3].x, d2);
                d3 = ffma2(wreg[m+3].y, hv[m+3].y, d3);
            }
            float dp = pairsum(d0) + pairsum(d1) + pairsum(d2) + pairsum(d3);
            sp[tid] = dp + ((lay == 1) ? upart[tt][tid] : u);
            __syncthreads();
            if (tid < 256) {
                float zv = sp[tid] + sp[tid + 256] + biasr;
                float a = (jg >= 256 && jg < 384) ? fast_tanh(zv) : fast_sigmoid(zv);
                int zl = (int)rank * 256 + tid;
                zact[buf][zl] = a;
                unsigned int la = smem_u32(&zact[buf][zl]);
                unsigned int ra;
                asm volatile("mapa.shared::cluster.u32 %0, %1, %2;"
                             : "=r"(ra) : "r"(la), "r"(peer));
                asm volatile("st.shared::cluster.f32 [%0], %1;"
                             :: "r"(ra), "f"(a) : "memory");
            }
            asm volatile("barrier.cluster.arrive.aligned;" ::: "memory");
            asm volatile("barrier.cluster.wait.aligned;" ::: "memory");
            if (tid < Hdim) {
                float ai = zact[buf][tid],       af = zact[buf][128 + tid];
                float ag = zact[buf][256 + tid], ao = zact[buf][384 + tid];
                float cn = af * cs[tid] + ai * ag;
                float hn = ao * fast_tanh(cn);
                cs[tid] = cn;
                hs[tid] = hn;
                if (rank == 0) hout[t * Hdim + tid] = hn;
            }
            __syncthreads();
        }

        if (lay == 0 && rank == 0) {
            // publish: every storer fences its h1 stores, then one thread bumps the flag
            __threadfence();
            __syncthreads();
            if (tid == 0) atomicExch(&g_prog[br][b], (unsigned)((c + 1) * CH));
        }
    }
}

// ---------------- kernel 6: weighted sum + layernorm ----------------
__global__ void final_kernel(const float* __restrict__ sum_w,
                             const float* __restrict__ ln_g,
                             const float* __restrict__ ln_b,
                             float* __restrict__ out) {
    int row = blockIdx.x, tid = threadIdx.x;
    float w0 = sum_w[0], w1 = sum_w[1], w2 = sum_w[2];
    float inv = 1.f / (w0 + w1 + w2);
    float v = (w0 * g_h2[0][row * Hdim + tid]
             + w1 * g_h2[1][row * Hdim + tid]
             + w2 * g_h2[2][row * Hdim + tid]) * inv;
    __shared__ float buf[128];
    float m = bredsum(v, buf) * (1.f / Hdim);
    float d = v - m;
    float var = bredsum(d * d, buf) * (1.f / Hdim);
    out[row * Hdim + tid] = d * rsqrtf(var + EPSV) * ln_g[tid] + ln_b[tid];
}

// ---------------- launch ----------------
extern "C" void kernel_launch(void* const* d_in, const int* in_sizes, int n_in,
                              void* d_out, int out_size) {
    const float* x          = (const float*)d_in[0];
    const float* attn_w     = (const float*)d_in[1];
    const float* attn_scale = (const float*)d_in[2];
    const float* Wq         = (const float*)d_in[3];
    const float* Wk         = (const float*)d_in[4];
    const float* bk         = (const float*)d_in[5];
    const float* Wv         = (const float*)d_in[6];
    const float* bn1g = (const float*)d_in[7],  *bn1b = (const float*)d_in[8];
    const float* bn2g = (const float*)d_in[9],  *bn2b = (const float*)d_in[10];
    const float* bn3g = (const float*)d_in[11], *bn3b = (const float*)d_in[12];
    const float* l1_Wih = (const float*)d_in[13], *l1_Whh = (const float*)d_in[14];
    const float* l1_bih = (const float*)d_in[15], *l1_bhh = (const float*)d_in[16];
    const float* l2_Wih = (const float*)d_in[17], *l2_Whh = (const float*)d_in[18];
    const float* l2_bih = (const float*)d_in[19], *l2_bhh = (const float*)d_in[20];
    const float* l3_Wih = (const float*)d_in[21], *l3_Whh = (const float*)d_in[22];
    const float* l3_bih = (const float*)d_in[23], *l3_bhh = (const float*)d_in[24];
    const float* ln_g  = (const float*)d_in[25];
    const float* ln_b  = (const float*)d_in[26];
    const float* sum_w = (const float*)d_in[27];
    float* out = (float*)d_out;

    transpose_kernel<<<dim3(32, 12), 512>>>(l1_Wih, l1_Whh, l2_Wih, l2_Whh, l3_Wih, l3_Whh);
    qkv_kernel<<<dim3(256, 3), 128>>>(x, Wq, Wk, bk, Wv);
    attn_kernel<<<dim3(Ldim, Bdim), 128>>>(x, attn_w, attn_scale);
    bnstat_kernel<<<dim3(128, 3), 256>>>(x, bn1g, bn1b, bn2g, bn2b, bn3g, bn3b);
    uproj_kernel<<<dim3(512, 3), 512>>>(x,
        l1_bih, l1_bhh, l2_bih, l2_bhh, l3_bih, l3_bhh);
    scan_fused<<<dim3(2, Bdim, 6), 512>>>(
        l1_bih, l1_bhh, l2_bih, l2_bhh, l3_bih, l3_bhh);
    final_kernel<<<NROWS, 128>>>(sum_w, ln_g, ln_b, out);
}